// round 5
// baseline (speedup 1.0000x reference)
#include <cuda_runtime.h>
#include <cstdint>

#define NUM_CLASSES 19
#define C_DIM 256
#define HW 16384
#define BS 8
#define Q_DIM 2975
#define NJ 4               // q-splits in lse
#define QCH 744            // ceil(2975/4)
#define ARG_BLOCKS 512     // BS*HW/256
#define INV_T 5.0f
#define LOG2E 1.4426950408889634f

// scratch (allocation-free __device__ globals; every slot fully rewritten each
// run -> no init kernel, and all reductions are deterministic)
__device__ float g_psums[BS][NUM_CLASSES][C_DIM];     // pool partials per batch
__device__ int   g_pcnt[ARG_BLOCKS][NUM_CLASSES];     // argmax per-block counts
__device__ float g_keys[NUM_CLASSES * C_DIM];
__device__ int   g_counts[NUM_CLASSES];
__device__ float g_psexp[NJ][NUM_CLASSES][C_DIM];     // lse partials per q-chunk
__device__ float g_logit0[NUM_CLASSES * C_DIM];       // keys*q0/T (nat domain)
__device__ __align__(16) unsigned char g_pred[BS * HW];
__device__ int   g_bar_pool = 0;                      // self-resetting counters
__device__ int   g_bar_lse  = 0;

// ---------------------------------------------------------------------------
// 1) argmax per pixel + copy res->out + per-block class counts (no atomics to
//    global, no init dependency)
// ---------------------------------------------------------------------------
__global__ void __launch_bounds__(256) k_argmax(const float* __restrict__ res,
                                                float* __restrict__ out,
                                                int do_copy) {
    __shared__ int scnt[NUM_CLASSES];
    int tid = threadIdx.x;
    if (tid < NUM_CLASSES) scnt[tid] = 0;
    __syncthreads();

    int pg = blockIdx.x * 256 + tid;          // 0 .. BS*HW-1
    int b  = pg >> 14;
    int p  = pg & (HW - 1);
    int base = b * NUM_CLASSES * HW + p;

    float best = res[base];
    if (do_copy) out[base] = best;
    int bk = 0;
#pragma unroll
    for (int k = 1; k < NUM_CLASSES; k++) {
        float v = res[base + k * HW];
        if (do_copy) out[base + k * HW] = v;
        if (v > best) { best = v; bk = k; }   // strict > == jnp.argmax tie rule
    }
    g_pred[pg] = (unsigned char)bk;
    atomicAdd(&scnt[bk], 1);
    __syncthreads();
    if (tid < NUM_CLASSES) g_pcnt[blockIdx.x][tid] = scnt[tid];
}

// ---------------------------------------------------------------------------
// 2) masked per-class pooling -> per-batch partials; LAST block additionally
//    reduces counts + partials and computes normalized keys (fused k_keys).
// ---------------------------------------------------------------------------
__global__ void __launch_bounds__(256) k_pool(const float* __restrict__ fea) {
    __shared__ float acc[NUM_CLASSES * 256];   // 19 KB; bank = tid%32, no conflicts
    __shared__ int is_last;
    int tid = threadIdx.x;
    int c = blockIdx.x, b = blockIdx.y;

#pragma unroll
    for (int k = 0; k < NUM_CLASSES; k++) acc[k * 256 + tid] = 0.f;
    __syncthreads();

    const float4* f4 = (const float4*)(fea + ((b * C_DIM + c) << 14));
    const uchar4* sp = (const uchar4*)(g_pred + b * HW);
#pragma unroll 4
    for (int i = tid; i < HW / 4; i += 256) {
        float4 v = f4[i];
        uchar4 cl = __ldg(sp + i);
        acc[cl.x * 256 + tid] += v.x;
        acc[cl.y * 256 + tid] += v.y;
        acc[cl.z * 256 + tid] += v.z;
        acc[cl.w * 256 + tid] += v.w;
    }
    __syncthreads();

    for (int s = 128; s > 0; s >>= 1) {
        if (tid < s) {
#pragma unroll
            for (int k = 0; k < NUM_CLASSES; k++)
                acc[k * 256 + tid] += acc[k * 256 + tid + s];
        }
        __syncthreads();
    }
    if (tid < NUM_CLASSES) g_psums[b][tid][c] = acc[tid * 256];

    // ---- last-block-done: fused keys computation ----
    __threadfence();
    __syncthreads();
    if (tid == 0)
        is_last = (atomicAdd(&g_bar_pool, 1) == (int)(gridDim.x * gridDim.y) - 1);
    __syncthreads();
    if (!is_last) return;
    if (tid == 0) g_bar_pool = 0;              // reset for next graph replay

    int w = tid >> 5, lane = tid & 31;
    for (int k = w; k < NUM_CLASSES; k += 8) {
        // reduce counts over the 512 argmax blocks
        int cnt = 0;
#pragma unroll
        for (int i = lane; i < ARG_BLOCKS; i += 32) cnt += g_pcnt[i][k];
#pragma unroll
        for (int o = 16; o; o >>= 1) cnt += __shfl_xor_sync(0xffffffffu, cnt, o);
        float inv_cnt = 1.0f / fmaxf((float)cnt, 1.0f);

        // reduce sums over BS batch partials; normalize along C
        float v[8];
        float sq = 0.f;
#pragma unroll
        for (int i = 0; i < 8; i++) {
            int ch = i * 32 + lane;
            float s = 0.f;
#pragma unroll
            for (int bb = 0; bb < BS; bb++) s += g_psums[bb][k][ch];
            v[i] = s * inv_cnt;
            sq += v[i] * v[i];
        }
#pragma unroll
        for (int o = 16; o; o >>= 1) sq += __shfl_xor_sync(0xffffffffu, sq, o);
        float inv_norm = 1.0f / fmaxf(sqrtf(sq), 1e-12f);
#pragma unroll
        for (int i = 0; i < 8; i++)
            g_keys[k * 256 + i * 32 + lane] = v[i] * inv_norm;
        if (lane == 0) g_counts[k] = cnt;
    }
}

// ---------------------------------------------------------------------------
// 3) fused qsum + sum-of-exp over q-chunks; (c, j=0) blocks also stash
//    logit0 = keys*q0/T.  LAST block reduces partials and computes the loss.
//    Single pass over queues (58 MB).
// ---------------------------------------------------------------------------
__global__ void __launch_bounds__(256) k_lse(const float* __restrict__ queues,
                                             float* __restrict__ out, int loss_idx) {
    __shared__ float red[NUM_CLASSES][8];
    __shared__ float red1[8];
    __shared__ int is_last;
    int tid = threadIdx.x, c = blockIdx.x, j = blockIdx.y;
    int lane = tid & 31, w = tid >> 5;
    int q0 = j * QCH;
    int q1 = min(q0 + QCH, Q_DIM);

    const float* qc = queues + c * Q_DIM;
    const int kstride = C_DIM * Q_DIM;

    float a[NUM_CLASSES];
#pragma unroll
    for (int k = 0; k < NUM_CLASSES; k++)
        a[k] = g_keys[k * 256 + c] * (INV_T * LOG2E);

    if (j == 0 && tid == 0) {
#pragma unroll
        for (int k = 0; k < NUM_CLASSES; k++)
            g_logit0[k * 256 + c] = (a[k] * (1.0f / LOG2E)) * __ldg(qc + k * kstride);
    }

    float acc[NUM_CLASSES];
#pragma unroll
    for (int k = 0; k < NUM_CLASSES; k++) acc[k] = 0.f;

    for (int q = q0 + tid; q < q1; q += 256) {
        float u[NUM_CLASSES];
        float s = 0.f;
#pragma unroll
        for (int k = 0; k < NUM_CLASSES; k++) { u[k] = __ldg(qc + k * kstride + q); s += u[k]; }
#pragma unroll
        for (int k = 0; k < NUM_CLASSES; k++) {
            float v1 = a[k] * u[k];
            float v2 = a[k] * s - v1;
            float e1, e2;
            asm("ex2.approx.f32 %0, %1;" : "=f"(e1) : "f"(v1));
            asm("ex2.approx.f32 %0, %1;" : "=f"(e2) : "f"(v2));
            acc[k] += e1 + e2;
        }
    }

#pragma unroll
    for (int k = 0; k < NUM_CLASSES; k++)
#pragma unroll
        for (int o = 16; o; o >>= 1) acc[k] += __shfl_down_sync(0xffffffffu, acc[k], o);

    if (lane == 0) {
#pragma unroll
        for (int k = 0; k < NUM_CLASSES; k++) red[k][w] = acc[k];
    }
    __syncthreads();
    if (tid < NUM_CLASSES) {
        float s = 0.f;
#pragma unroll
        for (int i = 0; i < 8; i++) s += red[tid][i];
        g_psexp[j][tid][c] = s;
    }

    // ---- last-block-done: fused loss ----
    __threadfence();
    __syncthreads();
    if (tid == 0)
        is_last = (atomicAdd(&g_bar_lse, 1) == (int)(gridDim.x * gridDim.y) - 1);
    __syncthreads();
    if (!is_last) return;
    if (tid == 0) g_bar_lse = 0;               // reset for next graph replay

    int ch = tid;                               // channel
    float tot = 0.f;
#pragma unroll
    for (int k = 0; k < NUM_CLASSES; k++) {
        if (g_counts[k] > 0) {
            float S = 0.f;
#pragma unroll
            for (int jj = 0; jj < NJ; jj++) S += g_psexp[jj][k][ch];
            tot += logf(S) - g_logit0[k * 256 + ch];
        }
    }
#pragma unroll
    for (int o = 16; o; o >>= 1) tot += __shfl_down_sync(0xffffffffu, tot, o);
    if (lane == 0) red1[w] = tot;
    __syncthreads();
    if (tid == 0) {
        float s = 0.f;
#pragma unroll
        for (int i = 0; i < 8; i++) s += red1[i];
        out[loss_idx] = s * (1.0f / (float)C_DIM);
    }
}

// ---------------------------------------------------------------------------
extern "C" void kernel_launch(void* const* d_in, const int* in_sizes, int n_in,
                              void* d_out, int out_size) {
    const float* fea    = (const float*)d_in[0];
    const float* res    = (const float*)d_in[1];
    const float* queues = (const float*)d_in[2];
    float* out = (float*)d_out;

    const int res_elems = BS * NUM_CLASSES * HW;
    int do_copy = (out_size > res_elems) ? 1 : 0;
    int loss_idx = (out_size > 0) ? (out_size - 1) : 0;

    k_argmax<<<ARG_BLOCKS, 256>>>(res, out, do_copy);
    k_pool<<<dim3(C_DIM, BS), 256>>>(fea);
    k_lse<<<dim3(C_DIM, NJ), 256>>>(queues, out, loss_idx);
}

// round 6
// speedup vs baseline: 1.0829x; 1.0829x over previous
#include <cuda_runtime.h>
#include <cstdint>

#define NUM_CLASSES 19
#define C_DIM 256
#define HW 16384
#define BS 8
#define Q_DIM 2975
#define NJ 4               // q-splits in lse
#define QCH 744            // ceil(2975/4)
#define ARG_BLOCKS 512     // BS*HW/256
#define INV_T 5.0f
#define LOG2E 1.4426950408889634f

// scratch (allocation-free __device__ globals)
__device__ float g_sums[NUM_CLASSES * C_DIM];          // zeroed by k_argmax
__device__ float g_sumexp[NUM_CLASSES * C_DIM];        // zeroed by k_argmax
__device__ int   g_pcnt[ARG_BLOCKS][NUM_CLASSES];      // per-block counts (overwritten)
__device__ int   g_counts[NUM_CLASSES];                // written by k_keys
__device__ float g_keys[NUM_CLASSES * C_DIM];
__device__ float g_logit0[NUM_CLASSES * C_DIM];        // keys*q0/T (nat domain)
__device__ __align__(16) unsigned char g_pred[BS * HW];

// ---------------------------------------------------------------------------
// 1) argmax per pixel + copy res->out + per-block class counts.
//    Two-phase: batch all 19 loads (MLP=19), then compare+store.
//    Block 0 zeroes the float accumulators used by later kernels.
// ---------------------------------------------------------------------------
__global__ void __launch_bounds__(256) k_argmax(const float* __restrict__ res,
                                                float* __restrict__ out,
                                                int do_copy) {
    __shared__ int scnt[NUM_CLASSES];
    int tid = threadIdx.x;
    if (blockIdx.x == 0) {
        for (int j = tid; j < NUM_CLASSES * C_DIM; j += 256) {
            g_sums[j] = 0.f;
            g_sumexp[j] = 0.f;
        }
    }
    if (tid < NUM_CLASSES) scnt[tid] = 0;
    __syncthreads();

    int pg = blockIdx.x * 256 + tid;          // 0 .. BS*HW-1
    int b  = pg >> 14;
    int p  = pg & (HW - 1);
    int base = b * NUM_CLASSES * HW + p;

    float v[NUM_CLASSES];
#pragma unroll
    for (int k = 0; k < NUM_CLASSES; k++) v[k] = res[base + k * HW];

    float best = v[0];
    int bk = 0;
#pragma unroll
    for (int k = 1; k < NUM_CLASSES; k++)
        if (v[k] > best) { best = v[k]; bk = k; }   // strict > == jnp.argmax ties
    if (do_copy) {
#pragma unroll
        for (int k = 0; k < NUM_CLASSES; k++) out[base + k * HW] = v[k];
    }
    g_pred[pg] = (unsigned char)bk;
    atomicAdd(&scnt[bk], 1);
    __syncthreads();
    if (tid < NUM_CLASSES) g_pcnt[blockIdx.x][tid] = scnt[tid];
}

// ---------------------------------------------------------------------------
// 2) masked per-class pooling: sums[k][c] += fea[b,c,p] where pred[b,p]==k
//    block=(c,b); pred served from L2 (128KB, reused 256x); per-thread smem
//    accumulators acc[k*256+tid] -> bank=tid%32, conflict-free. No tail code.
// ---------------------------------------------------------------------------
__global__ void __launch_bounds__(256) k_pool(const float* __restrict__ fea) {
    __shared__ float acc[NUM_CLASSES * 256];   // 19 KB
    int tid = threadIdx.x;
    int c = blockIdx.x, b = blockIdx.y;

#pragma unroll
    for (int k = 0; k < NUM_CLASSES; k++) acc[k * 256 + tid] = 0.f;
    __syncthreads();

    const float4* f4 = (const float4*)(fea + ((b * C_DIM + c) << 14));
    const uchar4* sp = (const uchar4*)(g_pred + b * HW);
#pragma unroll 4
    for (int i = tid; i < HW / 4; i += 256) {
        float4 v = f4[i];
        uchar4 cl = __ldg(sp + i);
        acc[cl.x * 256 + tid] += v.x;
        acc[cl.y * 256 + tid] += v.y;
        acc[cl.z * 256 + tid] += v.z;
        acc[cl.w * 256 + tid] += v.w;
    }
    __syncthreads();

    for (int s = 128; s > 0; s >>= 1) {
        if (tid < s) {
#pragma unroll
            for (int k = 0; k < NUM_CLASSES; k++)
                acc[k * 256 + tid] += acc[k * 256 + tid + s];
        }
        __syncthreads();
    }
    if (tid < NUM_CLASSES) atomicAdd(&g_sums[tid * C_DIM + c], acc[tid * 256]);
}

// ---------------------------------------------------------------------------
// 3) counts reduction + keys = normalize(sums / max(count,1)) along C.
//    One warp per class (grid=19, block=32).
// ---------------------------------------------------------------------------
__global__ void __launch_bounds__(32) k_keys() {
    int k = blockIdx.x, lane = threadIdx.x;

    int cnt = 0;
    for (int i = lane; i < ARG_BLOCKS; i += 32) cnt += g_pcnt[i][k];
#pragma unroll
    for (int o = 16; o; o >>= 1) cnt += __shfl_xor_sync(0xffffffffu, cnt, o);
    if (lane == 0) g_counts[k] = cnt;
    float inv_cnt = 1.0f / fmaxf((float)cnt, 1.0f);

    float v[8];
    float sq = 0.f;
#pragma unroll
    for (int i = 0; i < 8; i++) {
        v[i] = g_sums[k * 256 + i * 32 + lane] * inv_cnt;
        sq += v[i] * v[i];
    }
#pragma unroll
    for (int o = 16; o; o >>= 1) sq += __shfl_xor_sync(0xffffffffu, sq, o);
    float inv_norm = 1.0f / fmaxf(sqrtf(sq), 1e-12f);
#pragma unroll
    for (int i = 0; i < 8; i++)
        g_keys[k * 256 + i * 32 + lane] = v[i] * inv_norm;
}

// ---------------------------------------------------------------------------
// 4) fused qsum + logits + sum-of-exp.  Block=(c, qchunk of 4).
//    Single pass over queues (58 MB); partials via atomicAdd into g_sumexp.
//    j==0 blocks also stash logit0 = keys*q0/T for k_loss.
// ---------------------------------------------------------------------------
__global__ void __launch_bounds__(256) k_lse(const float* __restrict__ queues) {
    int tid = threadIdx.x, c = blockIdx.x, j = blockIdx.y;
    int lane = tid & 31, w = tid >> 5;
    int q0 = j * QCH;
    int q1 = min(q0 + QCH, Q_DIM);

    const float* qc = queues + c * Q_DIM;
    const int kstride = C_DIM * Q_DIM;

    float a[NUM_CLASSES];
#pragma unroll
    for (int k = 0; k < NUM_CLASSES; k++)
        a[k] = g_keys[k * 256 + c] * (INV_T * LOG2E);

    if (j == 0 && tid == 0) {
#pragma unroll
        for (int k = 0; k < NUM_CLASSES; k++)
            g_logit0[k * 256 + c] = (a[k] * (1.0f / LOG2E)) * __ldg(qc + k * kstride);
    }

    float acc[NUM_CLASSES];
#pragma unroll
    for (int k = 0; k < NUM_CLASSES; k++) acc[k] = 0.f;

    for (int q = q0 + tid; q < q1; q += 256) {
        float u[NUM_CLASSES];
        float s = 0.f;
#pragma unroll
        for (int k = 0; k < NUM_CLASSES; k++) { u[k] = __ldg(qc + k * kstride + q); s += u[k]; }
#pragma unroll
        for (int k = 0; k < NUM_CLASSES; k++) {
            float v1 = a[k] * u[k];
            float v2 = a[k] * s - v1;
            float e1, e2;
            asm("ex2.approx.f32 %0, %1;" : "=f"(e1) : "f"(v1));
            asm("ex2.approx.f32 %0, %1;" : "=f"(e2) : "f"(v2));
            acc[k] += e1 + e2;
        }
    }

#pragma unroll
    for (int k = 0; k < NUM_CLASSES; k++)
#pragma unroll
        for (int o = 16; o; o >>= 1) acc[k] += __shfl_down_sync(0xffffffffu, acc[k], o);

    __shared__ float red[NUM_CLASSES][8];
    if (lane == 0) {
#pragma unroll
        for (int k = 0; k < NUM_CLASSES; k++) red[k][w] = acc[k];
    }
    __syncthreads();
    if (tid < NUM_CLASSES) {
        float s = 0.f;
#pragma unroll
        for (int i = 0; i < 8; i++) s += red[tid][i];
        atomicAdd(&g_sumexp[tid * 256 + c], s);
    }
}

// ---------------------------------------------------------------------------
// 5) loss = (1/C) * sum over present classes, channels of (ln S - logit0)
//    All operands L2-resident scratch — no scattered DRAM reads.
// ---------------------------------------------------------------------------
__global__ void __launch_bounds__(256) k_loss(float* __restrict__ out, int loss_idx) {
    int tid = threadIdx.x;        // channel c
    float tot = 0.f;
#pragma unroll
    for (int k = 0; k < NUM_CLASSES; k++) {
        if (g_counts[k] > 0) {
            int idx = k * 256 + tid;
            tot += logf(g_sumexp[idx]) - g_logit0[idx];
        }
    }
    int lane = tid & 31, w = tid >> 5;
#pragma unroll
    for (int o = 16; o; o >>= 1) tot += __shfl_down_sync(0xffffffffu, tot, o);
    __shared__ float red[8];
    if (lane == 0) red[w] = tot;
    __syncthreads();
    if (tid == 0) {
        float s = 0.f;
#pragma unroll
        for (int i = 0; i < 8; i++) s += red[i];
        out[loss_idx] = s * (1.0f / (float)C_DIM);
    }
}

// ---------------------------------------------------------------------------
extern "C" void kernel_launch(void* const* d_in, const int* in_sizes, int n_in,
                              void* d_out, int out_size) {
    const float* fea    = (const float*)d_in[0];
    const float* res    = (const float*)d_in[1];
    const float* queues = (const float*)d_in[2];
    float* out = (float*)d_out;

    const int res_elems = BS * NUM_CLASSES * HW;
    int do_copy = (out_size > res_elems) ? 1 : 0;
    int loss_idx = (out_size > 0) ? (out_size - 1) : 0;

    k_argmax<<<ARG_BLOCKS, 256>>>(res, out, do_copy);
    k_pool<<<dim3(C_DIM, BS), 256>>>(fea);
    k_keys<<<NUM_CLASSES, 32>>>();
    k_lse<<<dim3(C_DIM, NJ), 256>>>(queues);
    k_loss<<<1, 256>>>(out, loss_idx);
}